// round 1
// baseline (speedup 1.0000x reference)
#include <cuda_runtime.h>

#define BB 64
#define TT 48
#define NN 184
#define FF 16
#define HIDD 64
#define EMBD 16
#define DCONV 33
#define BN 11776            // BB*NN
#define EE 141312           // BN*12
#define NWARP 20
#define NTHREADS 640
#define ROWS 4
#define NTILES (BN/ROWS)    // 2944

// shared memory layout (float offsets)
#define OFF_WROOT 0
#define OFF_WREL  2112
#define OFF_WIH   4224
#define OFF_WHH   22848
#define OFF_BCONV 35136
#define OFF_BIH   35200
#define OFF_BHH   35392
#define OFF_FCW   35584
#define OFF_WARP  35648
#define WARP_FLOATS 776     // xin 4*97 + agg 4*33 + hprev 4*64
#define SMEM_FLOATS (OFF_WARP + NWARP*WARP_FLOATS)
#define SMEM_BYTES  (SMEM_FLOATS*4)

// persistent scratch
__device__ float g_xn[2][BN];
__device__ float g_h[2][BN*HIDD];
__device__ int   g_ptr[BN+1];
__device__ int   g_cnt[BN];
__device__ int   g_srce[EE];
__device__ float g_we[EE];
__device__ unsigned g_arrive;
__device__ unsigned g_release;

extern __shared__ float smem[];

__device__ __forceinline__ float sigm(float x)      { return 1.0f/(1.0f+__expf(-x)); }
__device__ __forceinline__ float tanh_fast(float x) { return 2.0f/(1.0f+__expf(-2.0f*x)) - 1.0f; }

// sense-free monotonic grid barrier (all 1-block/SM blocks co-resident)
__device__ __forceinline__ void gridsync(unsigned &tgt) {
  __threadfence();
  __syncthreads();
  if (threadIdx.x == 0) {
    unsigned old = atomicAdd(&g_arrive, 1u);
    if (old == gridDim.x - 1) {
      atomicExch(&g_arrive, 0u);
      __threadfence();
      atomicAdd(&g_release, 1u);
    } else {
      while (atomicAdd(&g_release, 0u) < tgt) __nanosleep(64);
    }
  }
  __syncthreads();
  __threadfence();
  tgt++;
}

// fetch element d (0..32) of the conv input row: [xn, y, Xc(15), emb(16)]
__device__ __forceinline__ float fetch_elem(
    const float* __restrict__ X, const float* __restrict__ Y,
    const float* __restrict__ emb, const float* __restrict__ xnp,
    int row, int d, int t)
{
  if (d == 0) return __ldcg(xnp + row);
  int b = row / NN;
  int n = row - b * NN;
  int base = (b * TT + t) * NN + n;
  if (d == 1) return __ldg(Y + base);
  const float* xr = X + (long)base * FF;
  if (d < 17) return __ldg(xr + (d - 2));
  int idx = (int)__ldg(xr + (FF - 1));
  return __ldg(emb + idx * EMBD + (d - 17));
}

__global__ void __launch_bounds__(NTHREADS, 1)
encoder_kernel(const float* __restrict__ X, const float* __restrict__ Y,
               const float* __restrict__ emb,
               const float* __restrict__ Wroot, const float* __restrict__ Wrel,
               const float* __restrict__ bconv,
               const float* __restrict__ Wih, const float* __restrict__ Whh,
               const float* __restrict__ bih, const float* __restrict__ bhh,
               const float* __restrict__ fcw, const float* __restrict__ fcb,
               const float* __restrict__ ewt, const int* __restrict__ ei,
               float* __restrict__ outH, float* __restrict__ outP)
{
  unsigned tgt = *((volatile unsigned*)&g_release) + 1u;

  const int tid   = threadIdx.x;
  const int gsize = gridDim.x * NTHREADS;
  const int gtid  = blockIdx.x * NTHREADS + tid;

  // cache all weights in SMEM
  for (int i = tid; i < 2112;   i += NTHREADS) smem[OFF_WROOT + i] = Wroot[i];
  for (int i = tid; i < 2112;   i += NTHREADS) smem[OFF_WREL  + i] = Wrel[i];
  for (int i = tid; i < 97*192; i += NTHREADS) smem[OFF_WIH   + i] = Wih[i];
  for (int i = tid; i < 64*192; i += NTHREADS) smem[OFF_WHH   + i] = Whh[i];
  for (int i = tid; i < 64;     i += NTHREADS) smem[OFF_BCONV + i] = bconv[i];
  for (int i = tid; i < 192;    i += NTHREADS) smem[OFF_BIH   + i] = bih[i];
  for (int i = tid; i < 192;    i += NTHREADS) smem[OFF_BHH   + i] = bhh[i];
  for (int i = tid; i < 64;     i += NTHREADS) smem[OFF_FCW   + i] = fcw[i];
  const float fcbv = __ldg(fcb);

  // init state buffers + CSR counts
  for (int i = gtid; i < BN*HIDD; i += gsize) g_h[0][i] = 0.0f;
  for (int i = gtid; i < BN;      i += gsize) { g_xn[0][i] = 0.0f; g_cnt[i] = 0; }
  gridsync(tgt);

  // in-degree count
  for (int e = gtid; e < EE; e += gsize) atomicAdd(&g_cnt[__ldg(ei + EE + e)], 1);
  gridsync(tgt);

  // exclusive scan by block 0
  if (blockIdx.x == 0) {
    __shared__ int sscan[NTHREADS];
    int carry = 0;
    for (int c0 = 0; c0 < BN; c0 += NTHREADS) {
      int i = c0 + tid;
      int v = (i < BN) ? __ldcg(&g_cnt[i]) : 0;
      sscan[tid] = v;
      __syncthreads();
      for (int off = 1; off < NTHREADS; off <<= 1) {
        int tv = (tid >= off) ? sscan[tid - off] : 0;
        __syncthreads();
        sscan[tid] += tv;
        __syncthreads();
      }
      if (i < BN) { g_ptr[i] = carry + sscan[tid] - v; g_cnt[i] = 0; }
      int tot = sscan[NTHREADS - 1];
      __syncthreads();
      carry += tot;
    }
    if (tid == 0) g_ptr[BN] = carry;
  }
  gridsync(tgt);

  // scatter edges into CSR (by dst)
  for (int e = gtid; e < EE; e += gsize) {
    int d = __ldg(ei + EE + e);
    int pos = __ldcg(&g_ptr[d]) + atomicAdd(&g_cnt[d], 1);
    g_srce[pos] = __ldg(ei + e);
    g_we[pos]   = __ldg(ewt + e);
  }
  gridsync(tgt);

  const int warp = tid >> 5;
  const int lane = tid & 31;
  const int gwarp  = blockIdx.x * NWARP + warp;
  const int twarps = gridDim.x * NWARP;
  float* xin_s = smem + OFF_WARP + warp * WARP_FLOATS;  // [4][97] : xf | g
  float* agg_s = xin_s + 4*97;                          // [4][33]
  float* hpr_s = agg_s + 4*DCONV;                       // [4][64]

  for (int t = 0; t < TT; ++t) {
    const float* __restrict__ xnp = g_xn[t & 1];
    float*       __restrict__ xnc = g_xn[(t + 1) & 1];
    const float* __restrict__ hp  = g_h[t & 1];
    float*       __restrict__ hc  = g_h[(t + 1) & 1];

    for (int tile = gwarp; tile < NTILES; tile += twarps) {
      const int r0 = tile * ROWS;

      // stage 1a: own xf rows
      for (int e = lane; e < ROWS * DCONV; e += 32) {
        int rr = e / DCONV;
        int d  = e - rr * DCONV;
        xin_s[rr * 97 + d] = fetch_elem(X, Y, emb, xnp, r0 + rr, d, t);
      }
      // stage 1b: weighted neighbor aggregation (gather CSR, rebuild src feats on the fly)
      for (int e = lane; e < ROWS * DCONV; e += 32) {
        int rr = e / DCONV;
        int d  = e - rr * DCONV;
        int row = r0 + rr;
        int p0 = __ldcg(&g_ptr[row]);
        int p1 = __ldcg(&g_ptr[row + 1]);
        float acc = 0.0f;
        for (int p = p0; p < p1; ++p) {
          float w = __ldcg(&g_we[p]);
          int   s = __ldcg(&g_srce[p]);
          acc += w * fetch_elem(X, Y, emb, xnp, s, d, t);
        }
        agg_s[rr * DCONV + d] = acc;
      }
      // stage 1c: h_prev rows
      for (int i = lane; i < ROWS * HIDD; i += 32) {
        int rr = i >> 6;
        int c  = i & 63;
        hpr_s[rr * HIDD + c] = __ldcg(hp + (long)(r0 + rr) * HIDD + c);
      }
      __syncwarp();

      // stage 2: g = sigmoid(xf@Wroot + agg@Wrel + b)  (lane -> cols {lane, lane+32})
      {
        float a[2*ROWS];
        float b0 = smem[OFF_BCONV + lane];
        float b1 = smem[OFF_BCONV + lane + 32];
        #pragma unroll
        for (int rr = 0; rr < ROWS; ++rr) { a[rr*2] = b0; a[rr*2+1] = b1; }
        const float* WR = smem + OFF_WROOT;
        const float* WL = smem + OFF_WREL;
        #pragma unroll 3
        for (int k = 0; k < DCONV; ++k) {
          float w0 = WR[k*64 + lane], w1 = WR[k*64 + lane + 32];
          float v0 = WL[k*64 + lane], v1 = WL[k*64 + lane + 32];
          #pragma unroll
          for (int rr = 0; rr < ROWS; ++rr) {
            float xv = xin_s[rr*97 + k];
            float av = agg_s[rr*DCONV + k];
            a[rr*2]   += xv * w0 + av * v0;
            a[rr*2+1] += xv * w1 + av * v1;
          }
        }
        #pragma unroll
        for (int rr = 0; rr < ROWS; ++rr) {
          xin_s[rr*97 + DCONV + lane]      = sigm(a[rr*2]);
          xin_s[rr*97 + DCONV + lane + 32] = sigm(a[rr*2+1]);
        }
      }
      __syncwarp();

      // stage 3/4: gx = xin@Wih + b_ih (+ hn@Whh + b_hh merged for r,z gates; hg kept apart)
      float gx[ROWS*6];
      float hg[ROWS*2];
      #pragma unroll
      for (int rr = 0; rr < ROWS; ++rr) {
        #pragma unroll
        for (int m = 0; m < 6; ++m)
          gx[rr*6+m] = smem[OFF_BIH + lane + 32*m] + ((m < 4) ? smem[OFF_BHH + lane + 32*m] : 0.0f);
        hg[rr*2+0] = smem[OFF_BHH + lane + 128];
        hg[rr*2+1] = smem[OFF_BHH + lane + 160];
      }
      {
        const float* WI = smem + OFF_WIH;
        #pragma unroll 2
        for (int k = 0; k < 97; ++k) {
          const float* wr = WI + k*192 + lane;
          float w0 = wr[0], w1 = wr[32], w2 = wr[64], w3 = wr[96], w4 = wr[128], w5 = wr[160];
          #pragma unroll
          for (int rr = 0; rr < ROWS; ++rr) {
            float xv = xin_s[rr*97 + k];
            gx[rr*6+0] += xv*w0; gx[rr*6+1] += xv*w1; gx[rr*6+2] += xv*w2;
            gx[rr*6+3] += xv*w3; gx[rr*6+4] += xv*w4; gx[rr*6+5] += xv*w5;
          }
        }
        const float* WH = smem + OFF_WHH;
        #pragma unroll 2
        for (int k = 0; k < 64; ++k) {
          const float* wr = WH + k*192 + lane;
          float w0 = wr[0], w1 = wr[32], w2 = wr[64], w3 = wr[96], w4 = wr[128], w5 = wr[160];
          #pragma unroll
          for (int rr = 0; rr < ROWS; ++rr) {
            float hv = hpr_s[rr*HIDD + k];
            gx[rr*6+0] += hv*w0; gx[rr*6+1] += hv*w1; gx[rr*6+2] += hv*w2;
            gx[rr*6+3] += hv*w3;
            hg[rr*2+0] += hv*w4; hg[rr*2+1] += hv*w5;
          }
        }
      }

      // stage 5: GRU + outputs
      #pragma unroll
      for (int rr = 0; rr < ROWS; ++rr) {
        int row = r0 + rr;
        float rg0 = sigm(gx[rr*6+0]);
        float rg1 = sigm(gx[rr*6+1]);
        float z0  = sigm(gx[rr*6+2]);
        float z1  = sigm(gx[rr*6+3]);
        float n0  = tanh_fast(gx[rr*6+4] + rg0 * hg[rr*2+0]);
        float n1  = tanh_fast(gx[rr*6+5] + rg1 * hg[rr*2+1]);
        float hp0 = hpr_s[rr*HIDD + lane];
        float hp1 = hpr_s[rr*HIDD + lane + 32];
        float h0 = (1.0f - z0) * n0 + z0 * hp0;
        float h1 = (1.0f - z1) * n1 + z1 * hp1;
        int b = row / NN;
        int n = row - b * NN;
        long obase = ((long)(b*TT + t) * NN + n);
        outH[obase*HIDD + lane]      = h0;
        outH[obase*HIDD + lane + 32] = h1;
        __stcg(hc + (long)row*HIDD + lane,      h0);
        __stcg(hc + (long)row*HIDD + lane + 32, h1);
        float contrib = h0 * smem[OFF_FCW + lane] + h1 * smem[OFF_FCW + lane + 32];
        #pragma unroll
        for (int s = 16; s > 0; s >>= 1) contrib += __shfl_xor_sync(0xffffffffu, contrib, s);
        if (lane == 0) {
          float xv = contrib + fcbv;
          __stcg(xnc + row, xv);
          outP[obase] = xv;
        }
      }
      __syncwarp();
    }
    gridsync(tgt);
  }
}

extern "C" void kernel_launch(void* const* d_in, const int* in_sizes, int n_in,
                              void* d_out, int out_size) {
  const float* X     = (const float*)d_in[0];
  const float* Y     = (const float*)d_in[1];
  const float* emb   = (const float*)d_in[2];
  const float* Wroot = (const float*)d_in[3];
  const float* Wrel  = (const float*)d_in[4];
  const float* bconv = (const float*)d_in[5];
  const float* Wih   = (const float*)d_in[6];
  const float* Whh   = (const float*)d_in[7];
  const float* bih   = (const float*)d_in[8];
  const float* bhh   = (const float*)d_in[9];
  const float* fcw   = (const float*)d_in[10];
  const float* fcb   = (const float*)d_in[11];
  const float* ewt   = (const float*)d_in[12];
  const int*   ei    = (const int*)d_in[13];
  float* outH = (float*)d_out;
  float* outP = outH + (long)BB * TT * NN * HIDD;

  int dev = 0;
  cudaGetDevice(&dev);
  int nsm = 148;
  cudaDeviceGetAttribute(&nsm, cudaDevAttrMultiProcessorCount, dev);

  cudaFuncSetAttribute(encoder_kernel,
                       cudaFuncAttributeMaxDynamicSharedMemorySize, SMEM_BYTES);
  encoder_kernel<<<nsm, NTHREADS, SMEM_BYTES>>>(
      X, Y, emb, Wroot, Wrel, bconv, Wih, Whh, bih, bhh, fcw, fcb, ewt, ei,
      outH, outP);
}

// round 2
// speedup vs baseline: 1.8364x; 1.8364x over previous
#include <cuda_runtime.h>

#define BB 64
#define TT 48
#define NN 184
#define FF 16
#define HIDD 64
#define DCONV 33
#define XFS 36              // padded row stride of xfs table
#define BN 11776            // BB*NN
#define EE 141312           // BN*12
#define NWARP 20
#define NTHREADS 640
#define ROWS 4
#define NTILES (BN/ROWS)    // 2944

// shared memory layout (float offsets) -- all even (8B alignment for float2)
#define OFF_WROOT 0
#define OFF_WREL  2112
#define OFF_WIH   4224
#define OFF_WHH   22848
#define OFF_BCONV 35136
#define OFF_BIH   35200
#define OFF_BHH   35392
#define OFF_FCW   35584
#define OFF_WARP  35648
#define WARP_FLOATS 776     // xin 4*97 + agg 4*33 + hprev 4*64
#define SMEM_FLOATS (OFF_WARP + NWARP*WARP_FLOATS)
#define SMEM_BYTES  (SMEM_FLOATS*4)

// persistent scratch
__device__ float g_xfs[(long)TT*BN*XFS];   // static conv features, d0 = 0
__device__ float g_xn[2][BN];
__device__ float g_h[2][BN*HIDD];
__device__ int   g_ptr[BN+1];
__device__ int   g_cnt[BN];
__device__ int   g_srce[EE];
__device__ float g_we[EE];
__device__ unsigned g_arrive;
__device__ unsigned g_release;

extern __shared__ float smem[];

typedef unsigned long long u64;

__device__ __forceinline__ u64 pk2(float x, float y) {
  u64 r; asm("mov.b64 %0, {%1, %2};" : "=l"(r) : "f"(x), "f"(y)); return r;
}
__device__ __forceinline__ void upk2(float &x, float &y, u64 v) {
  asm("mov.b64 {%0, %1}, %2;" : "=f"(x), "=f"(y) : "l"(v));
}
__device__ __forceinline__ u64 ffma2(u64 a, u64 b, u64 c) {
  u64 d; asm("fma.rn.f32x2 %0, %1, %2, %3;" : "=l"(d) : "l"(a), "l"(b), "l"(c)); return d;
}

__device__ __forceinline__ float sigm(float x)      { return 1.0f/(1.0f+__expf(-x)); }
__device__ __forceinline__ float tanh_fast(float x) { return 2.0f/(1.0f+__expf(-2.0f*x)) - 1.0f; }

__device__ __forceinline__ void gridsync(unsigned &tgt) {
  __threadfence();
  __syncthreads();
  if (threadIdx.x == 0) {
    unsigned old = atomicAdd(&g_arrive, 1u);
    if (old == gridDim.x - 1) {
      atomicExch(&g_arrive, 0u);
      __threadfence();
      atomicAdd(&g_release, 1u);
    } else {
      while (atomicAdd(&g_release, 0u) < tgt) __nanosleep(64);
    }
  }
  __syncthreads();
  __threadfence();
  tgt++;
}

__global__ void __launch_bounds__(NTHREADS, 1)
encoder_kernel(const float* __restrict__ X, const float* __restrict__ Y,
               const float* __restrict__ emb,
               const float* __restrict__ Wroot, const float* __restrict__ Wrel,
               const float* __restrict__ bconv,
               const float* __restrict__ Wih, const float* __restrict__ Whh,
               const float* __restrict__ bih, const float* __restrict__ bhh,
               const float* __restrict__ fcw, const float* __restrict__ fcb,
               const float* __restrict__ ewt, const int* __restrict__ ei,
               float* __restrict__ outH, float* __restrict__ outP)
{
  unsigned tgt = *((volatile unsigned*)&g_release) + 1u;

  const int tid   = threadIdx.x;
  const int gsize = gridDim.x * NTHREADS;
  const int gtid  = blockIdx.x * NTHREADS + tid;

  // ---- weights into SMEM, column-pair packed layout ----
  // conv weights: W2[k][lane] = (W[k][lane], W[k][lane+32])
  for (int i = tid; i < 33*64; i += NTHREADS) {
    int k = i >> 6, c = i & 63;
    int half = c >> 5, l = c & 31;
    smem[OFF_WROOT + (k*32 + l)*2 + half] = Wroot[i];
    smem[OFF_WREL  + (k*32 + l)*2 + half] = Wrel[i];
  }
  // gru weights: W2[k][j*32+lane] = (W[k][lane+64j], W[k][lane+64j+32])
  for (int i = tid; i < 97*192; i += NTHREADS) {
    int k = i / 192, c = i - k*192;
    int j = c >> 6, w = c & 63, half = w >> 5, l = w & 31;
    smem[OFF_WIH + (k*96 + j*32 + l)*2 + half] = Wih[i];
  }
  for (int i = tid; i < 64*192; i += NTHREADS) {
    int k = i / 192, c = i - k*192;
    int j = c >> 6, w = c & 63, half = w >> 5, l = w & 31;
    smem[OFF_WHH + (k*96 + j*32 + l)*2 + half] = Whh[i];
  }
  for (int i = tid; i < 64;  i += NTHREADS) smem[OFF_BCONV + i] = bconv[i];
  for (int i = tid; i < 192; i += NTHREADS) smem[OFF_BIH   + i] = bih[i];
  for (int i = tid; i < 192; i += NTHREADS) smem[OFF_BHH   + i] = bhh[i];
  for (int i = tid; i < 64;  i += NTHREADS) smem[OFF_FCW   + i] = fcw[i];
  const float fcbv = __ldg(fcb);

  // ---- precompute static conv features xfs[t][row][d], d0=0 ----
  for (int rt = gtid; rt < TT*BN; rt += gsize) {
    int t = rt / BN, row = rt - t*BN;
    int b = row / NN, n = row - b*NN;
    long base = ((long)(b*TT + t)*NN + n);
    float buf[XFS];
    buf[0] = 0.0f;
    buf[1] = __ldg(Y + base);
    const float* xr = X + base*FF;
    #pragma unroll
    for (int i = 0; i < 15; ++i) buf[2+i] = __ldg(xr + i);
    int idx = (int)__ldg(xr + 15);
    const float* er = emb + idx*16;
    #pragma unroll
    for (int i = 0; i < 16; ++i) buf[17+i] = __ldg(er + i);
    buf[33] = buf[34] = buf[35] = 0.0f;
    float4* dst = (float4*)(g_xfs + (long)rt*XFS);
    #pragma unroll
    for (int i = 0; i < 9; ++i)
      dst[i] = make_float4(buf[4*i], buf[4*i+1], buf[4*i+2], buf[4*i+3]);
  }

  // ---- init state + CSR build ----
  for (int i = gtid; i < BN*HIDD; i += gsize) g_h[0][i] = 0.0f;
  for (int i = gtid; i < BN;      i += gsize) { g_xn[0][i] = 0.0f; g_cnt[i] = 0; }
  gridsync(tgt);

  for (int e = gtid; e < EE; e += gsize) atomicAdd(&g_cnt[__ldg(ei + EE + e)], 1);
  gridsync(tgt);

  if (blockIdx.x == 0) {
    __shared__ int sscan[NTHREADS];
    int carry = 0;
    for (int c0 = 0; c0 < BN; c0 += NTHREADS) {
      int i = c0 + tid;
      int v = (i < BN) ? __ldcg(&g_cnt[i]) : 0;
      sscan[tid] = v;
      __syncthreads();
      for (int off = 1; off < NTHREADS; off <<= 1) {
        int tv = (tid >= off) ? sscan[tid - off] : 0;
        __syncthreads();
        sscan[tid] += tv;
        __syncthreads();
      }
      if (i < BN) { g_ptr[i] = carry + sscan[tid] - v; g_cnt[i] = 0; }
      int tot = sscan[NTHREADS - 1];
      __syncthreads();
      carry += tot;
    }
    if (tid == 0) g_ptr[BN] = carry;
  }
  gridsync(tgt);

  for (int e = gtid; e < EE; e += gsize) {
    int d = __ldg(ei + EE + e);
    int pos = __ldcg(&g_ptr[d]) + atomicAdd(&g_cnt[d], 1);
    g_srce[pos] = __ldg(ei + e);
    g_we[pos]   = __ldg(ewt + e);
  }
  gridsync(tgt);

  const int warp = tid >> 5;
  const int lane = tid & 31;
  const int gwarp  = blockIdx.x * NWARP + warp;
  const int twarps = gridDim.x * NWARP;
  float* xin_s = smem + OFF_WARP + warp * WARP_FLOATS;  // [4][97] : xf | g
  float* agg_s = xin_s + 4*97;                          // [4][33]
  float* hpr_s = agg_s + 4*DCONV;                       // [4][64]

  const u64* WROOT2 = (const u64*)(smem + OFF_WROOT);
  const u64* WREL2  = (const u64*)(smem + OFF_WREL);
  const u64* WIH2   = (const u64*)(smem + OFF_WIH);
  const u64* WHH2   = (const u64*)(smem + OFF_WHH);

  for (int t = 0; t < TT; ++t) {
    const float* __restrict__ xnp = g_xn[t & 1];
    float*       __restrict__ xnc = g_xn[(t + 1) & 1];
    const float* __restrict__ hp  = g_h[t & 1];
    float*       __restrict__ hc  = g_h[(t + 1) & 1];
    const float* __restrict__ xfs_t = g_xfs + (long)t*BN*XFS;

    for (int tile = gwarp; tile < NTILES; tile += twarps) {
      const int r0 = tile * ROWS;

      // stage 1: own xf rows + weighted neighbor aggregation + h_prev
      for (int e = lane; e < ROWS * DCONV; e += 32) {
        int rr = e / DCONV;
        int d  = e - rr * DCONV;
        int row = r0 + rr;
        // own row
        float own = (d == 0) ? __ldcg(xnp + row) : __ldg(xfs_t + (long)row*XFS + d);
        xin_s[rr * 97 + d] = own;
        // gather over in-edges
        int p0 = __ldcg(&g_ptr[row]);
        int p1 = __ldcg(&g_ptr[row + 1]);
        float acc = 0.0f;
        if (d == 0) {
          for (int p = p0; p < p1; ++p)
            acc += __ldcg(&g_we[p]) * __ldcg(xnp + __ldcg(&g_srce[p]));
        } else {
          const float* col = xfs_t + d;
          for (int p = p0; p < p1; ++p)
            acc += __ldcg(&g_we[p]) * __ldg(col + (long)__ldcg(&g_srce[p])*XFS);
        }
        agg_s[rr * DCONV + d] = acc;
      }
      for (int i = lane; i < ROWS * HIDD; i += 32) {
        int rr = i >> 6;
        int c  = i & 63;
        hpr_s[rr * HIDD + c] = __ldcg(hp + (long)(r0 + rr) * HIDD + c);
      }
      __syncwarp();

      // stage 2: g = sigmoid(xf@Wroot + agg@Wrel + b)  packed col-pair (lane, lane+32)
      {
        u64 a2[ROWS];
        u64 binit = pk2(smem[OFF_BCONV + lane], smem[OFF_BCONV + lane + 32]);
        #pragma unroll
        for (int rr = 0; rr < ROWS; ++rr) a2[rr] = binit;
        #pragma unroll 3
        for (int k = 0; k < DCONV; ++k) {
          u64 w2 = WROOT2[k*32 + lane];
          u64 v2 = WREL2 [k*32 + lane];
          #pragma unroll
          for (int rr = 0; rr < ROWS; ++rr) {
            u64 xv2 = pk2(xin_s[rr*97 + k], xin_s[rr*97 + k]);
            u64 av2 = pk2(agg_s[rr*DCONV + k], agg_s[rr*DCONV + k]);
            a2[rr] = ffma2(xv2, w2, ffma2(av2, v2, a2[rr]));
          }
        }
        #pragma unroll
        for (int rr = 0; rr < ROWS; ++rr) {
          float g0, g1; upk2(g0, g1, a2[rr]);
          xin_s[rr*97 + DCONV + lane]      = sigm(g0);
          xin_s[rr*97 + DCONV + lane + 32] = sigm(g1);
        }
      }
      __syncwarp();

      // stage 3/4: gru pre-activations, packed col-pairs
      // pair j covers cols (lane+64j, lane+64j+32): j=0 -> r, j=1 -> z, j=2 -> g
      u64 gx2[ROWS*3];
      u64 hg2[ROWS];
      {
        u64 b0 = pk2(smem[OFF_BIH + lane]       + smem[OFF_BHH + lane],
                     smem[OFF_BIH + lane + 32]  + smem[OFF_BHH + lane + 32]);
        u64 b1 = pk2(smem[OFF_BIH + lane + 64]  + smem[OFF_BHH + lane + 64],
                     smem[OFF_BIH + lane + 96]  + smem[OFF_BHH + lane + 96]);
        u64 b2 = pk2(smem[OFF_BIH + lane + 128], smem[OFF_BIH + lane + 160]);
        u64 bh = pk2(smem[OFF_BHH + lane + 128], smem[OFF_BHH + lane + 160]);
        #pragma unroll
        for (int rr = 0; rr < ROWS; ++rr) {
          gx2[rr*3+0] = b0; gx2[rr*3+1] = b1; gx2[rr*3+2] = b2; hg2[rr] = bh;
        }
      }
      #pragma unroll 2
      for (int k = 0; k < 97; ++k) {
        u64 w0 = WIH2[k*96 + lane];
        u64 w1 = WIH2[k*96 + 32 + lane];
        u64 w2 = WIH2[k*96 + 64 + lane];
        #pragma unroll
        for (int rr = 0; rr < ROWS; ++rr) {
          float xv = xin_s[rr*97 + k];
          u64 xv2 = pk2(xv, xv);
          gx2[rr*3+0] = ffma2(xv2, w0, gx2[rr*3+0]);
          gx2[rr*3+1] = ffma2(xv2, w1, gx2[rr*3+1]);
          gx2[rr*3+2] = ffma2(xv2, w2, gx2[rr*3+2]);
        }
      }
      #pragma unroll 2
      for (int k = 0; k < 64; ++k) {
        u64 w0 = WHH2[k*96 + lane];
        u64 w1 = WHH2[k*96 + 32 + lane];
        u64 w2 = WHH2[k*96 + 64 + lane];
        #pragma unroll
        for (int rr = 0; rr < ROWS; ++rr) {
          float hv = hpr_s[rr*HIDD + k];
          u64 hv2 = pk2(hv, hv);
          gx2[rr*3+0] = ffma2(hv2, w0, gx2[rr*3+0]);
          gx2[rr*3+1] = ffma2(hv2, w1, gx2[rr*3+1]);
          hg2[rr]     = ffma2(hv2, w2, hg2[rr]);
        }
      }

      // stage 5: GRU nonlinearity + outputs
      #pragma unroll
      for (int rr = 0; rr < ROWS; ++rr) {
        int row = r0 + rr;
        float xr0, xr1, xz0, xz1, xg0, xg1, hgv0, hgv1;
        upk2(xr0, xr1, gx2[rr*3+0]);
        upk2(xz0, xz1, gx2[rr*3+1]);
        upk2(xg0, xg1, gx2[rr*3+2]);
        upk2(hgv0, hgv1, hg2[rr]);
        float rg0 = sigm(xr0), rg1 = sigm(xr1);
        float z0  = sigm(xz0), z1  = sigm(xz1);
        float n0  = tanh_fast(xg0 + rg0 * hgv0);
        float n1  = tanh_fast(xg1 + rg1 * hgv1);
        float hp0 = hpr_s[rr*HIDD + lane];
        float hp1 = hpr_s[rr*HIDD + lane + 32];
        float h0 = (1.0f - z0) * n0 + z0 * hp0;
        float h1 = (1.0f - z1) * n1 + z1 * hp1;
        int b = row / NN;
        int n = row - b * NN;
        long obase = ((long)(b*TT + t) * NN + n);
        outH[obase*HIDD + lane]      = h0;
        outH[obase*HIDD + lane + 32] = h1;
        __stcg(hc + (long)row*HIDD + lane,      h0);
        __stcg(hc + (long)row*HIDD + lane + 32, h1);
        float contrib = h0 * smem[OFF_FCW + lane] + h1 * smem[OFF_FCW + lane + 32];
        #pragma unroll
        for (int s = 16; s > 0; s >>= 1) contrib += __shfl_xor_sync(0xffffffffu, contrib, s);
        if (lane == 0) {
          float xv = contrib + fcbv;
          __stcg(xnc + row, xv);
          outP[obase] = xv;
        }
      }
      __syncwarp();
    }
    gridsync(tgt);
  }
}

extern "C" void kernel_launch(void* const* d_in, const int* in_sizes, int n_in,
                              void* d_out, int out_size) {
  const float* X     = (const float*)d_in[0];
  const float* Y     = (const float*)d_in[1];
  const float* emb   = (const float*)d_in[2];
  const float* Wroot = (const float*)d_in[3];
  const float* Wrel  = (const float*)d_in[4];
  const float* bconv = (const float*)d_in[5];
  const float* Wih   = (const float*)d_in[6];
  const float* Whh   = (const float*)d_in[7];
  const float* bih   = (const float*)d_in[8];
  const float* bhh   = (const float*)d_in[9];
  const float* fcw   = (const float*)d_in[10];
  const float* fcb   = (const float*)d_in[11];
  const float* ewt   = (const float*)d_in[12];
  const int*   ei    = (const int*)d_in[13];
  float* outH = (float*)d_out;
  float* outP = outH + (long)BB * TT * NN * HIDD;

  int dev = 0;
  cudaGetDevice(&dev);
  int nsm = 148;
  cudaDeviceGetAttribute(&nsm, cudaDevAttrMultiProcessorCount, dev);

  cudaFuncSetAttribute(encoder_kernel,
                       cudaFuncAttributeMaxDynamicSharedMemorySize, SMEM_BYTES);
  encoder_kernel<<<nsm, NTHREADS, SMEM_BYTES>>>(
      X, Y, emb, Wroot, Wrel, bconv, Wih, Whh, bih, bhh, fcw, fcb, ewt, ei,
      outH, outP);
}